// round 15
// baseline (speedup 1.0000x reference)
#include <cuda_runtime.h>

namespace {
constexpr int T_ = 1024;
constexpr int S_ = 512;
constexpr int D_ = 32;
constexpr int K_ = 64;
constexpr float LOG2PI_F = 1.8378770664093453f;
constexpr float SHIFT = 72.0f;   // shift log-probs so per-step scale ~ O(1)
}

// Per-sequence total log-denominator (fp64 for the stable cross-sequence sum).
__device__ double g_logden[S_];

// ---- packed f32x2 helpers (sm_103a dual-lane fp32 pipe) ----
__device__ __forceinline__ unsigned long long fma2(unsigned long long a,
                                                   unsigned long long b,
                                                   unsigned long long c) {
    unsigned long long d;
    asm("fma.rn.f32x2 %0, %1, %2, %3;" : "=l"(d) : "l"(a), "l"(b), "l"(c));
    return d;
}
__device__ __forceinline__ unsigned long long add2(unsigned long long a,
                                                   unsigned long long b) {
    unsigned long long d;
    asm("add.rn.f32x2 %0, %1, %2;" : "=l"(d) : "l"(a), "l"(b));
    return d;
}
__device__ __forceinline__ unsigned long long pack2(float lo, float hi) {
    unsigned long long v;
    unsigned int l = __float_as_uint(lo), h = __float_as_uint(hi);
    asm("mov.b64 %0, {%1, %2};" : "=l"(v) : "r"(l), "r"(h));
    return v;
}
__device__ __forceinline__ float hsum2(unsigned long long v) {
    unsigned int l, h;
    asm("mov.b64 {%0, %1}, %2;" : "=r"(l), "=r"(h) : "l"(v));
    return __uint_as_float(l) + __uint_as_float(h);
}

__global__ void __launch_bounds__(K_) hmm_forward_kernel(
    const float* __restrict__ data,     // [T, S, D]
    const float* __restrict__ initp,    // [K]
    const float* __restrict__ trans,    // [K, K] row-stochastic
    const float* __restrict__ means,    // [K, D]
    const float* __restrict__ covars,   // [K, D]
    float* __restrict__ out)            // [S, K] alpha
{
    const int s = blockIdx.x;          // sequence
    const int k = threadIdx.x;         // state

    __shared__ __align__(16) float buf[2][K_];   // double-buffered (unnormalized) alpha
    __shared__ __align__(16) float xsh[2][D_];   // double-buffered observation

    // ---- per-state Gaussian parameters, packed as f32x2 pairs over d ----
    // logp_k(x) = sum_d x*(c1*x + c2) + ck, c1 = -0.5/cov, c2 = mu/cov
    unsigned long long c1p[D_ / 2], c2p[D_ / 2];
    float sq = 0.f, ld = 0.f;
    const float4* mrow = reinterpret_cast<const float4*>(means + k * D_);
    const float4* crow = reinterpret_cast<const float4*>(covars + k * D_);
#pragma unroll
    for (int q = 0; q < D_ / 4; ++q) {
        float4 mv = mrow[q];
        float4 cv = crow[q];
        float i0 = 1.0f / cv.x, i1 = 1.0f / cv.y, i2 = 1.0f / cv.z, i3 = 1.0f / cv.w;
        c1p[2*q + 0] = pack2(-0.5f * i0, -0.5f * i1);
        c1p[2*q + 1] = pack2(-0.5f * i2, -0.5f * i3);
        c2p[2*q + 0] = pack2(mv.x * i0, mv.y * i1);
        c2p[2*q + 1] = pack2(mv.z * i2, mv.w * i3);
        sq += mv.x * mv.x * i0 + mv.y * mv.y * i1 + mv.z * mv.z * i2 + mv.w * mv.w * i3;
        ld += __logf(cv.x) + __logf(cv.y) + __logf(cv.z) + __logf(cv.w);
    }
    const float ck = -0.5f * (sq + ld + (float)D_ * LOG2PI_F) + SHIFT;

    // Transition column k as f32x2 pairs over j: Ap[j2] = (A[2j2][k], A[2j2+1][k])
    unsigned long long Ap[K_ / 2];
#pragma unroll
    for (int j2 = 0; j2 < K_ / 2; ++j2)
        Ap[j2] = pack2(__ldg(trans + (2 * j2) * K_ + k),
                       __ldg(trans + (2 * j2 + 1) * K_ + k));

    // emission log-prob -> p = exp(logp + SHIFT), reading x from shared (f32x2)
    auto emit = [&](const float* xs) -> float {
        const ulonglong2* x2 = reinterpret_cast<const ulonglong2*>(xs);
        unsigned long long l0 = pack2(ck, 0.f), l1 = 0ULL, l2 = 0ULL, l3 = 0ULL;
#pragma unroll
        for (int i = 0; i < D_ / 4; ++i) {
            ulonglong2 xv = x2[i];
            unsigned long long t0 = fma2(c1p[2*i + 0], xv.x, c2p[2*i + 0]);
            unsigned long long t1 = fma2(c1p[2*i + 1], xv.y, c2p[2*i + 1]);
            if ((i & 1) == 0) { l0 = fma2(xv.x, t0, l0); l1 = fma2(xv.y, t1, l1); }
            else              { l2 = fma2(xv.x, t0, l2); l3 = fma2(xv.y, t1, l3); }
        }
        return __expf(hsum2(add2(add2(l0, l1), add2(l2, l3))));
    };

    // matvec m = (a @ A)[k] and d = sum(a) from the shared buffer (f32x2)
    auto matvec = [&](const float* bp, float& m, float& d) {
        const ulonglong2* b2 = reinterpret_cast<const ulonglong2*>(bp);
        unsigned long long m0 = 0ULL, m1 = 0ULL, m2 = 0ULL, m3 = 0ULL;
        unsigned long long d0 = 0ULL, d1 = 0ULL, d2 = 0ULL, d3 = 0ULL;
#pragma unroll
        for (int i = 0; i < K_ / 4; ++i) {
            ulonglong2 av = b2[i];
            if ((i & 1) == 0) {
                m0 = fma2(av.x, Ap[2*i + 0], m0);
                m1 = fma2(av.y, Ap[2*i + 1], m1);
                d0 = add2(d0, av.x);
                d1 = add2(d1, av.y);
            } else {
                m2 = fma2(av.x, Ap[2*i + 0], m2);
                m3 = fma2(av.y, Ap[2*i + 1], m3);
                d2 = add2(d2, av.x);
                d3 = add2(d3, av.y);
            }
        }
        m = hsum2(add2(add2(m0, m1), add2(m2, m3)));
        d = hsum2(add2(add2(d0, d1), add2(d2, d3)));
    };

    // ---- t = 0: a_0 = p_0 * initial_probs (unnormalized; d_0 summed next step) ----
    const float ipk = initp[k];
    if (k < D_ / 4)
        reinterpret_cast<uint4*>(xsh[0])[k] =
            reinterpret_cast<const uint4*>(data + (size_t)s * D_)[k];
    __syncthreads();

    float alast = emit(xsh[0]) * ipk;
    buf[0][k] = alast;
    if (k < D_ / 4)
        reinterpret_cast<uint4*>(xsh[1])[k] =
            reinterpret_cast<const uint4*>(data + ((size_t)S_ + s) * D_)[k];
    __syncthreads();

    float fll = 0.f;     // chunked log-denominator accumulator
    double dll = 0.0;

    for (int t = 1; t < T_; ++t) {
        const int cb = t & 1, pb = cb ^ 1;

        // early prefetch of x_{t+1} (address clamped at the end)
        uint4 gx;
        if (k < D_ / 4) {
            int tp = (t + 1 < T_) ? t + 1 : T_ - 1;
            gx = reinterpret_cast<const uint4*>(data + ((size_t)tp * S_ + s) * D_)[k];
        }

        float m, d;
        matvec(buf[pb], m, d);           // m̃ = a_{t-1}@A (unnormalized), d = d_{t-1}
        float p = emit(xsh[cb]);         // emission for time t (independent chain)
        float rinv = __fdividef(1.0f, d);
        fll += __logf(d);                // side chain only

        alast = p * m * rinv;            // = p_t ⊙ (alpha_{t-1}@A), unnormalized a_t
        buf[cb][k] = alast;
        if (k < D_ / 4)
            reinterpret_cast<uint4*>(xsh[pb])[k] = gx;

        if ((t & 31) == 0) { dll += (double)fll; fll = 0.f; }
        __syncthreads();                 // single barrier per step
    }

    // ---- final step: sum a_{T-1}, emit normalized alpha and total log-denom ----
    {
        float m, d;
        matvec(buf[(T_ - 1) & 1], m, d);
        fll += __logf(d);
        dll += (double)fll;
        dll -= (double)SHIFT * (double)T_;   // remove shift (one per time step)

        out[(size_t)s * K_ + k] = alast * __fdividef(1.0f, d);
        if (k == 0) g_logden[s] = dll;
    }
}

// Deterministic final reduction: nll = -sum_s logden[s]
__global__ void hmm_reduce_kernel(float* __restrict__ out, int out_size)
{
    __shared__ double sh[S_];
    int t = threadIdx.x;
    sh[t] = g_logden[t];
    __syncthreads();
#pragma unroll
    for (int off = S_ / 2; off > 0; off >>= 1) {
        if (t < off) sh[t] += sh[t + off];
        __syncthreads();
    }
    if (t == 0 && out_size > S_ * K_)
        out[S_ * K_] = (float)(-sh[0]);
}

extern "C" void kernel_launch(void* const* d_in, const int* in_sizes, int n_in,
                              void* d_out, int out_size)
{
    const float* data   = (const float*)d_in[0];
    const float* initp  = (const float*)d_in[1];
    const float* trans  = (const float*)d_in[2];
    const float* means  = (const float*)d_in[3];
    const float* covars = (const float*)d_in[4];
    float* out = (float*)d_out;

    hmm_forward_kernel<<<S_, K_>>>(data, initp, trans, means, covars, out);
    hmm_reduce_kernel<<<1, S_>>>(out, out_size);
}